// round 16
// baseline (speedup 1.0000x reference)
#include <cuda_runtime.h>
#include <cuda_bf16.h>
#include <math.h>

#define Bb 8
#define Tt 12
#define Nn 307
#define Dd 64
#define Hh 4
#define HDm 16
#define NSLICE (Hh*Bb*Tt)        /* 384 */
#define NN (Nn*Nn)               /* 94249 */
#define BTN (Bb*Tt*Nn)           /* 29472 */
#define BTND (BTN*Dd)            /* 1886208 */

#define LDP 320                  /* padded inner stride */
#define MR  384                  /* padded row count */
#define SLICE_CP (MR*LDP)        /* 122880 elems per slice */

// ---------------- scratch (static device globals; zero-init, no allocs) ----
__device__ float g_nadjP[MR*LDP];                  // tf32 bits of nadj [384][320]
__device__ float g_q2[BTND];
__device__ float g_k2[BTND];
__device__ float g_v2[BTND];
__device__ float g_qtP[Bb*Tt*LDP*Dd];              // tf32 bits of q@Wt^T [96][320][64]
__device__ float g_out1h[BTND];                    // 0.5*relu(graphconv)
__device__ __nv_bfloat16 g_Pb[(size_t)NSLICE*SLICE_CP];   // bf16 P
__device__ __nv_bfloat16 g_dynb[(size_t)NSLICE*SLICE_CP]; // bf16 P @ E_g
__device__ __nv_bfloat16 g_EgT[LDP*LDP];           // bf16 E_g TRANSPOSED [n][k]

__device__ __forceinline__ unsigned f2tf(float f) {
    unsigned u;
    asm("cvt.rna.tf32.f32 %0, %1;" : "=r"(u) : "f"(f));
    return u;
}

// ---------------- GEMM plumbing ------------------------------------------
#define BMt 128
#define ASTRc 36
#define BKg 32
#define STAGE_Ag (BMt*ASTRc)
#define BSTRg 72
#define STAGE_Bg (BKg*BSTRg)
#define GC_SMEM_BYTES ((2*STAGE_Ag + 2*STAGE_Bg)*4)   /* 55296 */
#define BKd 64
#define STAGE_Ad (BMt*ASTRc)
#define STAGE_Bd (64*ASTRc)
#define DYN_SMEM_BYTES ((2*STAGE_Ad + 2*STAGE_Bd)*4)  /* 55296 */

#define MMA_TF32(d0,d1,d2,d3,a0,a1,a2,a3,b0,b1) \
    asm volatile("mma.sync.aligned.m16n8k8.row.col.f32.tf32.tf32.f32 " \
                 "{%0,%1,%2,%3},{%4,%5,%6,%7},{%8,%9},{%0,%1,%2,%3};" \
                 : "+f"(d0),"+f"(d1),"+f"(d2),"+f"(d3) \
                 : "r"(a0),"r"(a1),"r"(a2),"r"(a3),"r"(b0),"r"(b1))

#define MMA_BF16(d0,d1,d2,d3,a0,a1,a2,a3,b0,b1) \
    asm volatile("mma.sync.aligned.m16n8k16.row.col.f32.bf16.bf16.f32 " \
                 "{%0,%1,%2,%3},{%4,%5,%6,%7},{%8,%9},{%0,%1,%2,%3};" \
                 : "+f"(d0),"+f"(d1),"+f"(d2),"+f"(d3) \
                 : "r"(a0),"r"(a1),"r"(a2),"r"(a3),"r"(b0),"r"(b1))

#define LDMATRIX_X4(r0,r1,r2,r3,addr) \
    asm volatile("ldmatrix.sync.aligned.m8n8.x4.shared.b16 {%0,%1,%2,%3}, [%4];" \
                 : "=r"(r0),"=r"(r1),"=r"(r2),"=r"(r3) : "r"(addr))

#define LDMATRIX_X2(r0,r1,addr) \
    asm volatile("ldmatrix.sync.aligned.m8n8.x2.shared.b16 {%0,%1}, [%2];" \
                 : "=r"(r0),"=r"(r1) : "r"(addr))

#define CP_ASYNC16(dst_u32, src_ptr) \
    asm volatile("cp.async.cg.shared.global [%0], [%1], 16;" :: "r"(dst_u32), "l"(src_ptr))

// ---------------- kernel 1: normalized adjacency -> padded tf32 -----------
__global__ void nadj_kernel(const float* __restrict__ adj) {
    int i = blockIdx.x;
    __shared__ float red[256];
    float s = 0.f;
    for (int j = threadIdx.x; j < Nn; j += 256) s += adj[i*Nn + j];
    red[threadIdx.x] = s; __syncthreads();
    for (int w = 128; w > 0; w >>= 1) {
        if (threadIdx.x < w) red[threadIdx.x] += red[threadIdx.x + w];
        __syncthreads();
    }
    float inv = 1.f / (red[0] + 1.f);
    for (int j = threadIdx.x; j < Nn; j += 256) {
        float v = (adj[i*Nn + j] + (j == i ? 1.f : 0.f)) * inv;
        g_nadjP[i*LDP + j] = __uint_as_float(f2tf(v));
    }
}

// ------- kernel 1b: pack E_g bf16 TRANSPOSED into [n=320][k=320] ----------
__global__ void egpack_kernel(const float* __restrict__ Eg) {
    int n = blockIdx.x;
    for (int k = threadIdx.x; k < LDP; k += 256) {
        float v = (n < Nn && k < Nn) ? Eg[k*Nn + n] : 0.f;
        g_EgT[n*LDP + k] = __float2bfloat16(v);
    }
}

// ---------------- kernel 2: batched linear X @ W^T (+ bias) ----------------
__global__ void linear_kernel(const float* __restrict__ query,
                              const float* __restrict__ key_in,
                              const float* __restrict__ value,
                              const float* __restrict__ Wq, const float* __restrict__ bq,
                              const float* __restrict__ Wk, const float* __restrict__ bk,
                              const float* __restrict__ Wv, const float* __restrict__ bv,
                              const float* __restrict__ Wt) {
    int which = blockIdx.z;
    const float* X; const float* W; const float* bias; float* out;
    if (which == 0)      { X = query;  W = Wq; bias = bq;      out = g_q2; }
    else if (which == 1) { X = key_in; W = Wk; bias = bk;      out = g_k2; }
    else if (which == 2) { X = value;  W = Wv; bias = bv;      out = g_v2; }
    else                 { X = query;  W = Wt; bias = nullptr; out = g_qtP; }

    __shared__ float Xs[64][65];
    __shared__ float Wts[64][65];
    int tid = threadIdx.x;
    int rowBase = blockIdx.x * 64;
    int rows = min(64, BTN - rowBase);

    for (int idx = tid; idx < 64*64; idx += 256) {
        int r = idx >> 6, c = idx & 63;
        Xs[r][c] = (r < rows) ? X[(size_t)(rowBase + r)*64 + c] : 0.f;
    }
    for (int idx = tid; idx < 64*64; idx += 256) {
        int j = idx >> 6, k = idx & 63;
        Wts[k][j] = W[idx];
    }
    __syncthreads();

    int ty = tid >> 4, tx = tid & 15;
    int r0 = ty*4, c0 = tx*4;
    float acc[4][4] = {};
    for (int k = 0; k < 64; k++) {
        float a[4], b4[4];
        #pragma unroll
        for (int i = 0; i < 4; i++) a[i] = Xs[r0 + i][k];
        #pragma unroll
        for (int j = 0; j < 4; j++) b4[j] = Wts[k][c0 + j];
        #pragma unroll
        for (int i = 0; i < 4; i++)
            #pragma unroll
            for (int j = 0; j < 4; j++) acc[i][j] += a[i]*b4[j];
    }
    #pragma unroll
    for (int i = 0; i < 4; i++) {
        int r = r0 + i;
        if (r < rows) {
            int gr = rowBase + r;
            if (which == 3) {
                int bt = gr / Nn, n = gr % Nn;
                size_t base = ((size_t)bt*LDP + n)*Dd;
                #pragma unroll
                for (int j = 0; j < 4; j++)
                    g_qtP[base + c0 + j] = __uint_as_float(f2tf(acc[i][j]));
            } else {
                #pragma unroll
                for (int j = 0; j < 4; j++)
                    out[(size_t)gr*64 + c0 + j] = acc[i][j] + bias[c0 + j];
            }
        }
    }
}

// ---------------- kernel 3: graph conv 0.5*relu(nadj@qt + bt), tf32 (R5) ----
__global__ __launch_bounds__(256, 4) void graphconv_tc(const float* __restrict__ btb) {
    extern __shared__ unsigned dsm[];
    unsigned* AsBase = dsm;
    unsigned* BsBase = dsm + 2*STAGE_Ag;

    int bt = blockIdx.x;
    int rowBase = blockIdx.y * BMt;
    const float* Bsrc = g_qtP + (size_t)bt*LDP*Dd;
    float* out = g_out1h + (size_t)bt*Nn*Dd;

    int tid = threadIdx.x, lane = tid & 31, warp = tid >> 5;
    int wm = warp & 3, wn = warp >> 2;
    int gid = lane >> 2, tig = lane & 3;

    int am  = tid >> 3;
    int akq = (tid & 7) * 4;
    int bk  = tid >> 4;
    int bnq = (tid & 15) * 4;

    unsigned aSm = (unsigned)__cvta_generic_to_shared(AsBase);
    unsigned bSm = (unsigned)__cvta_generic_to_shared(BsBase);

    float c[2][4][4] = {};

    auto load_tiles = [&](int kt, int s) {
        unsigned aDst = aSm + (unsigned)(s*STAGE_Ag)*4u;
        #pragma unroll
        for (int j = 0; j < 4; j++) {
            int row = am + 32*j;
            CP_ASYNC16(aDst + (unsigned)(row*ASTRc + akq)*4u,
                       g_nadjP + (size_t)(rowBase + row)*LDP + kt + akq);
        }
        unsigned bDst = bSm + (unsigned)(s*STAGE_Bg)*4u;
        #pragma unroll
        for (int j = 0; j < 2; j++) {
            int kk = bk + 16*j;
            CP_ASYNC16(bDst + (unsigned)(kk*BSTRg + bnq)*4u,
                       Bsrc + (size_t)(kt + kk)*Dd + bnq);
        }
    };

    load_tiles(0, 0);
    asm volatile("cp.async.commit_group;");

    const int NT = LDP / BKg;   // 10
    for (int it = 0; it < NT; it++) {
        if (it < NT - 1) {
            load_tiles((it + 1)*BKg, (it + 1) & 1);
            asm volatile("cp.async.commit_group;");
            asm volatile("cp.async.wait_group 1;");
        } else {
            asm volatile("cp.async.wait_group 0;");
        }
        __syncthreads();

        const unsigned* As = AsBase + (it & 1)*STAGE_Ag;
        const unsigned* Bs = BsBase + (it & 1)*STAGE_Bg;

        #pragma unroll
        for (int kb = 0; kb < BKg; kb += 8) {
            unsigned a[2][4], b[4][2];
            #pragma unroll
            for (int mi = 0; mi < 2; mi++) {
                int mb = wm*32 + mi*16;
                a[mi][0] = As[(mb + gid    )*ASTRc + kb + tig    ];
                a[mi][1] = As[(mb + gid + 8)*ASTRc + kb + tig    ];
                a[mi][2] = As[(mb + gid    )*ASTRc + kb + tig + 4];
                a[mi][3] = As[(mb + gid + 8)*ASTRc + kb + tig + 4];
            }
            #pragma unroll
            for (int ni = 0; ni < 4; ni++) {
                int nb = wn*32 + ni*8;
                b[ni][0] = Bs[(kb + tig    )*BSTRg + nb + gid];
                b[ni][1] = Bs[(kb + tig + 4)*BSTRg + nb + gid];
            }
            #pragma unroll
            for (int mi = 0; mi < 2; mi++)
                #pragma unroll
                for (int ni = 0; ni < 4; ni++)
                    MMA_TF32(c[mi][ni][0], c[mi][ni][1], c[mi][ni][2], c[mi][ni][3],
                             a[mi][0], a[mi][1], a[mi][2], a[mi][3],
                             b[ni][0], b[ni][1]);
        }
        __syncthreads();
    }

    #pragma unroll
    for (int mi = 0; mi < 2; mi++) {
        int r0 = rowBase + wm*32 + mi*16 + gid;
        #pragma unroll
        for (int ni = 0; ni < 4; ni++) {
            int col = wn*32 + ni*8 + tig*2;
            float b0 = btb[col], b1 = btb[col + 1];
            if (r0 < Nn)
                *(float2*)&out[(size_t)r0*Dd + col] = make_float2(
                    0.5f*fmaxf(c[mi][ni][0] + b0, 0.f), 0.5f*fmaxf(c[mi][ni][1] + b1, 0.f));
            if (r0 + 8 < Nn)
                *(float2*)&out[(size_t)(r0 + 8)*Dd + col] = make_float2(
                    0.5f*fmaxf(c[mi][ni][2] + b0, 0.f), 0.5f*fmaxf(c[mi][ni][3] + b1, 0.f));
        }
    }
}

// ------- kernel 4: P = softmax(relu(Y Y^T / 8)) -> bf16 (occ 2, no spills) --
__global__ __launch_bounds__(256, 2) void pmat_kernel(const float* __restrict__ query) {
    int slice = blockIdx.y;
    int hb = slice / Tt, t = slice % Tt;
    int h = hb / Bb, b = hb % Bb;
    __shared__ float4 Ys4[Nn*5];
    const float* qbase = query + ((size_t)(b*Tt + t)*Nn)*Dd + h*HDm;
    for (int idx = threadIdx.x; idx < Nn*4; idx += 256) {
        int n = idx >> 2, q = idx & 3;
        Ys4[n*5 + q] = *(const float4*)(qbase + (size_t)n*Dd + q*4);
    }
    __syncthreads();

    int warp = threadIdx.x >> 5, lane = threadIdx.x & 31;
    int rstart = blockIdx.x * 77;
    int rend = min(Nn, rstart + 77);
    __nv_bfloat16* Pb = g_Pb + (size_t)slice*SLICE_CP;

    for (int n = rstart + warp; n < rend; n += 8) {
        float4 qn[4];
        #pragma unroll
        for (int q = 0; q < 4; q++) qn[q] = Ys4[n*5 + q];
        float e[10]; float mx = -1e30f;
        #pragma unroll
        for (int k = 0; k < 10; k++) {
            int m = lane + 32*k;
            float s = -1e30f;
            if (m < Nn) {
                float a = 0.f;
                #pragma unroll
                for (int q = 0; q < 4; q++) {
                    float4 km = Ys4[m*5 + q];
                    a += qn[q].x*km.x + qn[q].y*km.y + qn[q].z*km.z + qn[q].w*km.w;
                }
                s = fmaxf(a * 0.125f, 0.f);
            }
            e[k] = s; mx = fmaxf(mx, s);
        }
        #pragma unroll
        for (int o = 16; o; o >>= 1) mx = fmaxf(mx, __shfl_xor_sync(0xffffffffu, mx, o));
        float sum = 0.f;
        #pragma unroll
        for (int k = 0; k < 10; k++) { float v = __expf(e[k] - mx); e[k] = v; sum += v; }
        #pragma unroll
        for (int o = 16; o; o >>= 1) sum += __shfl_xor_sync(0xffffffffu, sum, o);
        float inv = 1.f / sum;
        #pragma unroll
        for (int k = 0; k < 10; k++) {
            int m = lane + 32*k;
            Pb[(size_t)n*LDP + m] = __float2bfloat16(e[k]*inv);
        }
    }
}

// -------- kernel 5: dyn = P @ E_g, bf16 m16n8k16 + ldmatrix, bf16 output ----
__global__ __launch_bounds__(256, 4) void dyn_gemm_tc() {
    extern __shared__ unsigned dsm[];
    unsigned* AsBase = dsm;
    unsigned* BsBase = dsm + 2*STAGE_Ad;

    int slice = blockIdx.z;
    const __nv_bfloat16* A = g_Pb + (size_t)slice*SLICE_CP;
    __nv_bfloat16* Cout = g_dynb + (size_t)slice*SLICE_CP;
    int rowBase = blockIdx.y * BMt;
    int colBase = blockIdx.x * 64;

    int tid = threadIdx.x, lane = tid & 31, warp = tid >> 5;
    int wm = warp & 3, wn = warp >> 2;
    int gid = lane >> 2, tig = lane & 3;

    int arow = tid >> 3;
    int aq   = (tid & 7) * 8;
    int brow = tid >> 3;

    unsigned aSm = (unsigned)__cvta_generic_to_shared(AsBase);
    unsigned bSm = (unsigned)__cvta_generic_to_shared(BsBase);

    // ldmatrix per-lane fragment offsets (bytes)
    // A x4: j=lane>>3 -> row (j&1)*8 + (lane&7), kpair (j>>1)*4
    unsigned aFragOff = (unsigned)(((((lane >> 3) & 1)*8 + (lane & 7))*ASTRc
                                    + (lane >> 4)*4))*4u;
    // B x2: lanes 0-15 -> row lane&7, kpair ((lane>>3)&1)*4 (lanes>=16 replicate)
    unsigned bFragOff = (unsigned)(((lane & 7)*ASTRc + ((lane >> 3) & 1)*4))*4u;

    float c[2][4][4] = {};

    auto load_tiles = [&](int kt, int s) {
        unsigned aDst = aSm + (unsigned)(s*STAGE_Ad)*4u;
        #pragma unroll
        for (int j = 0; j < 4; j++) {
            int row = arow + 32*j;
            CP_ASYNC16(aDst + (unsigned)(row*ASTRc)*4u + (unsigned)aq*2u,
                       A + (size_t)(rowBase + row)*LDP + kt + aq);
        }
        unsigned bDst = bSm + (unsigned)(s*STAGE_Bd)*4u;
        #pragma unroll
        for (int j = 0; j < 2; j++) {
            int n = brow + 32*j;
            CP_ASYNC16(bDst + (unsigned)(n*ASTRc)*4u + (unsigned)aq*2u,
                       g_EgT + (size_t)(colBase + n)*LDP + kt + aq);
        }
    };

    load_tiles(0, 0);
    asm volatile("cp.async.commit_group;");

    const int NT = LDP / BKd;   // 5
    for (int it = 0; it < NT; it++) {
        if (it < NT - 1) {
            load_tiles((it + 1)*BKd, (it + 1) & 1);
            asm volatile("cp.async.commit_group;");
            asm volatile("cp.async.wait_group 1;");
        } else {
            asm volatile("cp.async.wait_group 0;");
        }
        __syncthreads();

        unsigned aStage = aSm + (unsigned)((it & 1)*STAGE_Ad)*4u;
        unsigned bStage = bSm + (unsigned)((it & 1)*STAGE_Bd)*4u;

        #pragma unroll
        for (int kb = 0; kb < 32; kb += 8) {
            unsigned a[2][4], b[4][2];
            #pragma unroll
            for (int mi = 0; mi < 2; mi++) {
                unsigned addr = aStage + (unsigned)(((wm*32 + mi*16)*ASTRc + kb))*4u
                              + aFragOff;
                LDMATRIX_X4(a[mi][0], a[mi][1], a[mi][2], a[mi][3], addr);
            }
            #pragma unroll
            for (int ni = 0; ni < 4; ni++) {
                unsigned addr = bStage + (unsigned)(((wn*32 + ni*8)*ASTRc + kb))*4u
                              + bFragOff;
                LDMATRIX_X2(b[ni][0], b[ni][1], addr);
            }
            #pragma unroll
            for (int mi = 0; mi < 2; mi++)
                #pragma unroll
                for (int ni = 0; ni < 4; ni++)
                    MMA_BF16(c[mi][ni][0], c[mi][ni][1], c[mi][ni][2], c[mi][ni][3],
                             a[mi][0], a[mi][1], a[mi][2], a[mi][3],
                             b[ni][0], b[ni][1]);
        }
        __syncthreads();
    }

    #pragma unroll
    for (int mi = 0; mi < 2; mi++) {
        int r0 = rowBase + wm*32 + mi*16 + gid;
        #pragma unroll
        for (int ni = 0; ni < 4; ni++) {
            int col = colBase + wn*32 + ni*8 + tig*2;
            *(__nv_bfloat162*)&Cout[(size_t)r0*LDP + col] =
                __floats2bfloat162_rn(c[mi][ni][0], c[mi][ni][1]);
            *(__nv_bfloat162*)&Cout[(size_t)(r0 + 8)*LDP + col] =
                __floats2bfloat162_rn(c[mi][ni][2], c[mi][ni][3]);
        }
    }
}

// ------- kernel 6: attention + tanh + merge + combine (occ 2, no spills) ----
#define ATTN_SMEM_BYTES (2*Nn*5*16 + 16)
__global__ __launch_bounds__(256, 2) void attn_kernel(float* __restrict__ out) {
    extern __shared__ float4 kv4[];
    float4* Ks4 = kv4;
    float4* Vs4 = kv4 + Nn*5 + 1;
    int slice = blockIdx.y;
    int hb = slice / Tt, t = slice % Tt;
    int h = hb / Bb, b = hb % Bb;
    size_t sl_off = ((size_t)(b*Tt + t)*Nn)*Dd + h*HDm;
    const float* kbase = g_k2 + sl_off;
    const float* vbase = g_v2 + sl_off;
    const float* qbase = g_q2 + sl_off;
    for (int idx = threadIdx.x; idx < Nn*4; idx += 256) {
        int n = idx >> 2, q = idx & 3;
        Ks4[n*5 + q] = *(const float4*)(kbase + (size_t)n*Dd + q*4);
        Vs4[n*5 + q] = *(const float4*)(vbase + (size_t)n*Dd + q*4);
    }
    __syncthreads();

    int warp = threadIdx.x >> 5, lane = threadIdx.x & 31;
    int rstart = blockIdx.x * 77;
    int rend = min(Nn, rstart + 77);
    const __nv_bfloat16* dynb = g_dynb + (size_t)slice*SLICE_CP;

    for (int n = rstart + warp; n < rend; n += 8) {
        float4 qn[4];
        #pragma unroll
        for (int q = 0; q < 4; q++) qn[q] = *(const float4*)(qbase + (size_t)n*Dd + q*4);
        float e[10]; float mx = -1e30f;
        #pragma unroll
        for (int k = 0; k < 10; k++) {
            int m = lane + 32*k;
            float s = -1e30f;
            if (m < Nn) {
                float a = 0.f;
                #pragma unroll
                for (int q = 0; q < 4; q++) {
                    float4 km = Ks4[m*5 + q];
                    a += qn[q].x*km.x + qn[q].y*km.y + qn[q].z*km.z + qn[q].w*km.w;
                }
                s = (a * 0.25f) * __bfloat162float(dynb[(size_t)n*LDP + m]);
            }
            e[k] = s; mx = fmaxf(mx, s);
        }
        #pragma unroll
        for (int o = 16; o; o >>= 1) mx = fmaxf(mx, __shfl_xor_sync(0xffffffffu, mx, o));
        float sum = 0.f;
        #pragma unroll
        for (int k = 0; k < 10; k++) { float v = __expf(e[k] - mx); e[k] = v; sum += v; }
        #pragma unroll
        for (int o = 16; o; o >>= 1) sum += __shfl_xor_sync(0xffffffffu, sum, o);
        float inv = 1.f / sum;

        float4 acc[4];
        #pragma unroll
        for (int q = 0; q < 4; q++) acc[q] = make_float4(0.f, 0.f, 0.f, 0.f);
        #pragma unroll
        for (int k = 0; k < 10; k++) {
            int m = lane + 32*k;
            if (m < Nn) {
                float w = e[k]*inv;
                #pragma unroll
                for (int q = 0; q < 4; q++) {
                    float4 vm = Vs4[m*5 + q];
                    acc[q].x += w*vm.x; acc[q].y += w*vm.y;
                    acc[q].z += w*vm.z; acc[q].w += w*vm.w;
                }
            }
        }
        float* accf = (float*)acc;
        #pragma unroll
        for (int d = 0; d < 16; d++) {
            #pragma unroll
            for (int o = 16; o; o >>= 1) accf[d] += __shfl_xor_sync(0xffffffffu, accf[d], o);
        }
        if (lane < 16) {
            size_t oidx = ((size_t)(b*Tt + t)*Nn + n)*Dd + h*HDm + lane;
            out[oidx] = g_out1h[oidx] + 0.5f * tanhf(accf[lane]);
        }
    }
}

// ---------------- launch ----------------
extern "C" void kernel_launch(void* const* d_in, const int* in_sizes, int n_in,
                              void* d_out, int out_size) {
    const float* query  = (const float*)d_in[0];
    const float* key_in = (const float*)d_in[1];
    const float* value  = (const float*)d_in[2];
    const float* adj    = (const float*)d_in[3];
    const float* Eg     = (const float*)d_in[4];
    const float* Wq     = (const float*)d_in[5];
    const float* bq     = (const float*)d_in[6];
    const float* Wk     = (const float*)d_in[7];
    const float* bk     = (const float*)d_in[8];
    const float* Wv     = (const float*)d_in[9];
    const float* bv     = (const float*)d_in[10];
    const float* Wt     = (const float*)d_in[11];
    const float* bt     = (const float*)d_in[12];
    float* out = (float*)d_out;

    cudaFuncSetAttribute(dyn_gemm_tc,
                         cudaFuncAttributeMaxDynamicSharedMemorySize, DYN_SMEM_BYTES);
    cudaFuncSetAttribute(graphconv_tc,
                         cudaFuncAttributeMaxDynamicSharedMemorySize, GC_SMEM_BYTES);
    cudaFuncSetAttribute(attn_kernel,
                         cudaFuncAttributeMaxDynamicSharedMemorySize, ATTN_SMEM_BYTES);

    nadj_kernel<<<Nn, 256>>>(adj);
    egpack_kernel<<<LDP, 256>>>(Eg);
    linear_kernel<<<dim3((BTN + 63)/64, 1, 4), 256>>>(query, key_in, value,
                                                      Wq, bq, Wk, bk, Wv, bv, Wt);
    graphconv_tc<<<dim3(Bb*Tt, 3), 256, GC_SMEM_BYTES>>>(bt);
    pmat_kernel<<<dim3(4, NSLICE), 256>>>(query);
    dyn_gemm_tc<<<dim3(5, 3, NSLICE), 256, DYN_SMEM_BYTES>>>();
    attn_kernel<<<dim3(4, NSLICE), 256, ATTN_SMEM_BYTES>>>(out);
}

// round 17
// speedup vs baseline: 1.0386x; 1.0386x over previous
#include <cuda_runtime.h>
#include <cuda_bf16.h>
#include <math.h>

#define Bb 8
#define Tt 12
#define Nn 307
#define Dd 64
#define Hh 4
#define HDm 16
#define NSLICE (Hh*Bb*Tt)        /* 384 */
#define NN (Nn*Nn)               /* 94249 */
#define BTN (Bb*Tt*Nn)           /* 29472 */
#define BTND (BTN*Dd)            /* 1886208 */

#define LDP 320                  /* padded inner stride */
#define MR  384                  /* padded row count */
#define SLICE_CP (MR*LDP)        /* 122880 elems per slice */

// ---------------- scratch (static device globals; zero-init, no allocs) ----
__device__ float g_nadjP[MR*LDP];                  // tf32 bits of nadj [384][320]
__device__ float g_q2[BTND];
__device__ float g_k2[BTND];
__device__ float g_v2[BTND];
__device__ float g_qtP[Bb*Tt*LDP*Dd];              // tf32 bits of q@Wt^T [96][320][64]
__device__ float g_out1h[BTND];                    // 0.5*relu(graphconv)
__device__ __nv_bfloat16 g_Pb[(size_t)NSLICE*SLICE_CP];   // bf16 P
__device__ __nv_bfloat16 g_dynb[(size_t)NSLICE*SLICE_CP]; // bf16 P @ E_g
__device__ __nv_bfloat16 g_EgT[LDP*LDP];           // bf16 E_g TRANSPOSED [n][k]

__device__ __forceinline__ unsigned f2tf(float f) {
    unsigned u;
    asm("cvt.rna.tf32.f32 %0, %1;" : "=r"(u) : "f"(f));
    return u;
}

// ---------------- GEMM plumbing ------------------------------------------
#define BMt 128
#define ASTRc 36
#define BKg 32
#define STAGE_Ag (BMt*ASTRc)
#define BSTRg 72
#define STAGE_Bg (BKg*BSTRg)
#define GC_SMEM_BYTES ((2*STAGE_Ag + 2*STAGE_Bg)*4)   /* 55296 */
#define BKd 64
#define STAGE_Ad (BMt*ASTRc)
#define STAGE_Bd (64*ASTRc)
#define DYN_SMEM_BYTES ((2*STAGE_Ad + 2*STAGE_Bd)*4)  /* 55296 */

#define MMA_TF32(d0,d1,d2,d3,a0,a1,a2,a3,b0,b1) \
    asm volatile("mma.sync.aligned.m16n8k8.row.col.f32.tf32.tf32.f32 " \
                 "{%0,%1,%2,%3},{%4,%5,%6,%7},{%8,%9},{%0,%1,%2,%3};" \
                 : "+f"(d0),"+f"(d1),"+f"(d2),"+f"(d3) \
                 : "r"(a0),"r"(a1),"r"(a2),"r"(a3),"r"(b0),"r"(b1))

#define MMA_BF16(d0,d1,d2,d3,a0,a1,a2,a3,b0,b1) \
    asm volatile("mma.sync.aligned.m16n8k16.row.col.f32.bf16.bf16.f32 " \
                 "{%0,%1,%2,%3},{%4,%5,%6,%7},{%8,%9},{%0,%1,%2,%3};" \
                 : "+f"(d0),"+f"(d1),"+f"(d2),"+f"(d3) \
                 : "r"(a0),"r"(a1),"r"(a2),"r"(a3),"r"(b0),"r"(b1))

#define CP_ASYNC16(dst_u32, src_ptr) \
    asm volatile("cp.async.cg.shared.global [%0], [%1], 16;" :: "r"(dst_u32), "l"(src_ptr))

// ---------------- kernel 1: normalized adjacency -> padded tf32 -----------
__global__ void nadj_kernel(const float* __restrict__ adj) {
    int i = blockIdx.x;
    __shared__ float red[256];
    float s = 0.f;
    for (int j = threadIdx.x; j < Nn; j += 256) s += adj[i*Nn + j];
    red[threadIdx.x] = s; __syncthreads();
    for (int w = 128; w > 0; w >>= 1) {
        if (threadIdx.x < w) red[threadIdx.x] += red[threadIdx.x + w];
        __syncthreads();
    }
    float inv = 1.f / (red[0] + 1.f);
    for (int j = threadIdx.x; j < Nn; j += 256) {
        float v = (adj[i*Nn + j] + (j == i ? 1.f : 0.f)) * inv;
        g_nadjP[i*LDP + j] = __uint_as_float(f2tf(v));
    }
}

// ------- kernel 1b: pack E_g bf16 TRANSPOSED into [n=320][k=320] ----------
__global__ void egpack_kernel(const float* __restrict__ Eg) {
    int n = blockIdx.x;
    for (int k = threadIdx.x; k < LDP; k += 256) {
        float v = (n < Nn && k < Nn) ? Eg[k*Nn + n] : 0.f;
        g_EgT[n*LDP + k] = __float2bfloat16(v);
    }
}

// ---------------- kernel 2: batched linear X @ W^T (+ bias) ----------------
__global__ void linear_kernel(const float* __restrict__ query,
                              const float* __restrict__ key_in,
                              const float* __restrict__ value,
                              const float* __restrict__ Wq, const float* __restrict__ bq,
                              const float* __restrict__ Wk, const float* __restrict__ bk,
                              const float* __restrict__ Wv, const float* __restrict__ bv,
                              const float* __restrict__ Wt) {
    int which = blockIdx.z;
    const float* X; const float* W; const float* bias; float* out;
    if (which == 0)      { X = query;  W = Wq; bias = bq;      out = g_q2; }
    else if (which == 1) { X = key_in; W = Wk; bias = bk;      out = g_k2; }
    else if (which == 2) { X = value;  W = Wv; bias = bv;      out = g_v2; }
    else                 { X = query;  W = Wt; bias = nullptr; out = g_qtP; }

    __shared__ float Xs[64][65];
    __shared__ float Wts[64][65];
    int tid = threadIdx.x;
    int rowBase = blockIdx.x * 64;
    int rows = min(64, BTN - rowBase);

    for (int idx = tid; idx < 64*64; idx += 256) {
        int r = idx >> 6, c = idx & 63;
        Xs[r][c] = (r < rows) ? X[(size_t)(rowBase + r)*64 + c] : 0.f;
    }
    for (int idx = tid; idx < 64*64; idx += 256) {
        int j = idx >> 6, k = idx & 63;
        Wts[k][j] = W[idx];
    }
    __syncthreads();

    int ty = tid >> 4, tx = tid & 15;
    int r0 = ty*4, c0 = tx*4;
    float acc[4][4] = {};
    for (int k = 0; k < 64; k++) {
        float a[4], b4[4];
        #pragma unroll
        for (int i = 0; i < 4; i++) a[i] = Xs[r0 + i][k];
        #pragma unroll
        for (int j = 0; j < 4; j++) b4[j] = Wts[k][c0 + j];
        #pragma unroll
        for (int i = 0; i < 4; i++)
            #pragma unroll
            for (int j = 0; j < 4; j++) acc[i][j] += a[i]*b4[j];
    }
    #pragma unroll
    for (int i = 0; i < 4; i++) {
        int r = r0 + i;
        if (r < rows) {
            int gr = rowBase + r;
            if (which == 3) {
                int bt = gr / Nn, n = gr % Nn;
                size_t base = ((size_t)bt*LDP + n)*Dd;
                #pragma unroll
                for (int j = 0; j < 4; j++)
                    g_qtP[base + c0 + j] = __uint_as_float(f2tf(acc[i][j]));
            } else {
                #pragma unroll
                for (int j = 0; j < 4; j++)
                    out[(size_t)gr*64 + c0 + j] = acc[i][j] + bias[c0 + j];
            }
        }
    }
}

// ---------------- kernel 3: graph conv 0.5*relu(nadj@qt + bt), tf32 (R5) ----
__global__ __launch_bounds__(256, 4) void graphconv_tc(const float* __restrict__ btb) {
    extern __shared__ unsigned dsm[];
    unsigned* AsBase = dsm;
    unsigned* BsBase = dsm + 2*STAGE_Ag;

    int bt = blockIdx.x;
    int rowBase = blockIdx.y * BMt;
    const float* Bsrc = g_qtP + (size_t)bt*LDP*Dd;
    float* out = g_out1h + (size_t)bt*Nn*Dd;

    int tid = threadIdx.x, lane = tid & 31, warp = tid >> 5;
    int wm = warp & 3, wn = warp >> 2;
    int gid = lane >> 2, tig = lane & 3;

    int am  = tid >> 3;
    int akq = (tid & 7) * 4;
    int bk  = tid >> 4;
    int bnq = (tid & 15) * 4;

    unsigned aSm = (unsigned)__cvta_generic_to_shared(AsBase);
    unsigned bSm = (unsigned)__cvta_generic_to_shared(BsBase);

    float c[2][4][4] = {};

    auto load_tiles = [&](int kt, int s) {
        unsigned aDst = aSm + (unsigned)(s*STAGE_Ag)*4u;
        #pragma unroll
        for (int j = 0; j < 4; j++) {
            int row = am + 32*j;
            CP_ASYNC16(aDst + (unsigned)(row*ASTRc + akq)*4u,
                       g_nadjP + (size_t)(rowBase + row)*LDP + kt + akq);
        }
        unsigned bDst = bSm + (unsigned)(s*STAGE_Bg)*4u;
        #pragma unroll
        for (int j = 0; j < 2; j++) {
            int kk = bk + 16*j;
            CP_ASYNC16(bDst + (unsigned)(kk*BSTRg + bnq)*4u,
                       Bsrc + (size_t)(kt + kk)*Dd + bnq);
        }
    };

    load_tiles(0, 0);
    asm volatile("cp.async.commit_group;");

    const int NT = LDP / BKg;   // 10
    for (int it = 0; it < NT; it++) {
        if (it < NT - 1) {
            load_tiles((it + 1)*BKg, (it + 1) & 1);
            asm volatile("cp.async.commit_group;");
            asm volatile("cp.async.wait_group 1;");
        } else {
            asm volatile("cp.async.wait_group 0;");
        }
        __syncthreads();

        const unsigned* As = AsBase + (it & 1)*STAGE_Ag;
        const unsigned* Bs = BsBase + (it & 1)*STAGE_Bg;

        #pragma unroll
        for (int kb = 0; kb < BKg; kb += 8) {
            unsigned a[2][4], b[4][2];
            #pragma unroll
            for (int mi = 0; mi < 2; mi++) {
                int mb = wm*32 + mi*16;
                a[mi][0] = As[(mb + gid    )*ASTRc + kb + tig    ];
                a[mi][1] = As[(mb + gid + 8)*ASTRc + kb + tig    ];
                a[mi][2] = As[(mb + gid    )*ASTRc + kb + tig + 4];
                a[mi][3] = As[(mb + gid + 8)*ASTRc + kb + tig + 4];
            }
            #pragma unroll
            for (int ni = 0; ni < 4; ni++) {
                int nb = wn*32 + ni*8;
                b[ni][0] = Bs[(kb + tig    )*BSTRg + nb + gid];
                b[ni][1] = Bs[(kb + tig + 4)*BSTRg + nb + gid];
            }
            #pragma unroll
            for (int mi = 0; mi < 2; mi++)
                #pragma unroll
                for (int ni = 0; ni < 4; ni++)
                    MMA_TF32(c[mi][ni][0], c[mi][ni][1], c[mi][ni][2], c[mi][ni][3],
                             a[mi][0], a[mi][1], a[mi][2], a[mi][3],
                             b[ni][0], b[ni][1]);
        }
        __syncthreads();
    }

    #pragma unroll
    for (int mi = 0; mi < 2; mi++) {
        int r0 = rowBase + wm*32 + mi*16 + gid;
        #pragma unroll
        for (int ni = 0; ni < 4; ni++) {
            int col = wn*32 + ni*8 + tig*2;
            float b0 = btb[col], b1 = btb[col + 1];
            if (r0 < Nn)
                *(float2*)&out[(size_t)r0*Dd + col] = make_float2(
                    0.5f*fmaxf(c[mi][ni][0] + b0, 0.f), 0.5f*fmaxf(c[mi][ni][1] + b1, 0.f));
            if (r0 + 8 < Nn)
                *(float2*)&out[(size_t)(r0 + 8)*Dd + col] = make_float2(
                    0.5f*fmaxf(c[mi][ni][2] + b0, 0.f), 0.5f*fmaxf(c[mi][ni][3] + b1, 0.f));
        }
    }
}

// ------- kernel 4: P = softmax(relu(Y Y^T / 8)) -> bf16 (occ 2, no spills) --
__global__ __launch_bounds__(256, 2) void pmat_kernel(const float* __restrict__ query) {
    int slice = blockIdx.y;
    int hb = slice / Tt, t = slice % Tt;
    int h = hb / Bb, b = hb % Bb;
    __shared__ float4 Ys4[Nn*5];
    const float* qbase = query + ((size_t)(b*Tt + t)*Nn)*Dd + h*HDm;
    for (int idx = threadIdx.x; idx < Nn*4; idx += 256) {
        int n = idx >> 2, q = idx & 3;
        Ys4[n*5 + q] = *(const float4*)(qbase + (size_t)n*Dd + q*4);
    }
    __syncthreads();

    int warp = threadIdx.x >> 5, lane = threadIdx.x & 31;
    int rstart = blockIdx.x * 77;
    int rend = min(Nn, rstart + 77);
    __nv_bfloat16* Pb = g_Pb + (size_t)slice*SLICE_CP;

    for (int n = rstart + warp; n < rend; n += 8) {
        float4 qn[4];
        #pragma unroll
        for (int q = 0; q < 4; q++) qn[q] = Ys4[n*5 + q];
        float e[10]; float mx = -1e30f;
        #pragma unroll
        for (int k = 0; k < 10; k++) {
            int m = lane + 32*k;
            float s = -1e30f;
            if (m < Nn) {
                float a = 0.f;
                #pragma unroll
                for (int q = 0; q < 4; q++) {
                    float4 km = Ys4[m*5 + q];
                    a += qn[q].x*km.x + qn[q].y*km.y + qn[q].z*km.z + qn[q].w*km.w;
                }
                s = fmaxf(a * 0.125f, 0.f);
            }
            e[k] = s; mx = fmaxf(mx, s);
        }
        #pragma unroll
        for (int o = 16; o; o >>= 1) mx = fmaxf(mx, __shfl_xor_sync(0xffffffffu, mx, o));
        float sum = 0.f;
        #pragma unroll
        for (int k = 0; k < 10; k++) { float v = __expf(e[k] - mx); e[k] = v; sum += v; }
        #pragma unroll
        for (int o = 16; o; o >>= 1) sum += __shfl_xor_sync(0xffffffffu, sum, o);
        float inv = 1.f / sum;
        #pragma unroll
        for (int k = 0; k < 10; k++) {
            int m = lane + 32*k;
            Pb[(size_t)n*LDP + m] = __float2bfloat16(e[k]*inv);
        }
    }
}

// -------- kernel 5: dyn = P @ E_g, bf16 m16n8k16, bf16 output (R15) --------
__global__ __launch_bounds__(256, 4) void dyn_gemm_tc() {
    extern __shared__ unsigned dsm[];
    unsigned* AsBase = dsm;
    unsigned* BsBase = dsm + 2*STAGE_Ad;

    int slice = blockIdx.z;
    const __nv_bfloat16* A = g_Pb + (size_t)slice*SLICE_CP;
    __nv_bfloat16* Cout = g_dynb + (size_t)slice*SLICE_CP;
    int rowBase = blockIdx.y * BMt;
    int colBase = blockIdx.x * 64;

    int tid = threadIdx.x, lane = tid & 31, warp = tid >> 5;
    int wm = warp & 3, wn = warp >> 2;
    int gid = lane >> 2, tig = lane & 3;

    int arow = tid >> 3;
    int aq   = (tid & 7) * 8;
    int brow = tid >> 3;

    unsigned aSm = (unsigned)__cvta_generic_to_shared(AsBase);
    unsigned bSm = (unsigned)__cvta_generic_to_shared(BsBase);

    float c[2][4][4] = {};

    auto load_tiles = [&](int kt, int s) {
        unsigned aDst = aSm + (unsigned)(s*STAGE_Ad)*4u;
        #pragma unroll
        for (int j = 0; j < 4; j++) {
            int row = arow + 32*j;
            CP_ASYNC16(aDst + (unsigned)(row*ASTRc)*4u + (unsigned)aq*2u,
                       A + (size_t)(rowBase + row)*LDP + kt + aq);
        }
        unsigned bDst = bSm + (unsigned)(s*STAGE_Bd)*4u;
        #pragma unroll
        for (int j = 0; j < 2; j++) {
            int n = brow + 32*j;
            CP_ASYNC16(bDst + (unsigned)(n*ASTRc)*4u + (unsigned)aq*2u,
                       g_EgT + (size_t)(colBase + n)*LDP + kt + aq);
        }
    };

    load_tiles(0, 0);
    asm volatile("cp.async.commit_group;");

    const int NT = LDP / BKd;   // 5
    for (int it = 0; it < NT; it++) {
        if (it < NT - 1) {
            load_tiles((it + 1)*BKd, (it + 1) & 1);
            asm volatile("cp.async.commit_group;");
            asm volatile("cp.async.wait_group 1;");
        } else {
            asm volatile("cp.async.wait_group 0;");
        }
        __syncthreads();

        const unsigned* As = AsBase + (it & 1)*STAGE_Ad;
        const unsigned* Bs = BsBase + (it & 1)*STAGE_Bd;

        #pragma unroll
        for (int kb = 0; kb < 32; kb += 8) {
            unsigned a[2][4], b[4][2];
            #pragma unroll
            for (int mi = 0; mi < 2; mi++) {
                int mb = wm*32 + mi*16;
                a[mi][0] = As[(mb + gid    )*ASTRc + kb + tig    ];
                a[mi][1] = As[(mb + gid + 8)*ASTRc + kb + tig    ];
                a[mi][2] = As[(mb + gid    )*ASTRc + kb + tig + 4];
                a[mi][3] = As[(mb + gid + 8)*ASTRc + kb + tig + 4];
            }
            #pragma unroll
            for (int ni = 0; ni < 4; ni++) {
                int nb = wn*32 + ni*8;
                b[ni][0] = Bs[(nb + gid)*ASTRc + kb + tig    ];
                b[ni][1] = Bs[(nb + gid)*ASTRc + kb + tig + 4];
            }
            #pragma unroll
            for (int mi = 0; mi < 2; mi++)
                #pragma unroll
                for (int ni = 0; ni < 4; ni++)
                    MMA_BF16(c[mi][ni][0], c[mi][ni][1], c[mi][ni][2], c[mi][ni][3],
                             a[mi][0], a[mi][1], a[mi][2], a[mi][3],
                             b[ni][0], b[ni][1]);
        }
        __syncthreads();
    }

    #pragma unroll
    for (int mi = 0; mi < 2; mi++) {
        int r0 = rowBase + wm*32 + mi*16 + gid;
        #pragma unroll
        for (int ni = 0; ni < 4; ni++) {
            int col = colBase + wn*32 + ni*8 + tig*2;
            *(__nv_bfloat162*)&Cout[(size_t)r0*LDP + col] =
                __floats2bfloat162_rn(c[mi][ni][0], c[mi][ni][1]);
            *(__nv_bfloat162*)&Cout[(size_t)(r0 + 8)*LDP + col] =
                __floats2bfloat162_rn(c[mi][ni][2], c[mi][ni][3]);
        }
    }
}

// ------- kernel 6: attention + tanh + merge + combine (occ 2, no spills) ----
#define ATTN_SMEM_BYTES (2*Nn*5*16 + 16)
__global__ __launch_bounds__(256, 2) void attn_kernel(float* __restrict__ out) {
    extern __shared__ float4 kv4[];
    float4* Ks4 = kv4;
    float4* Vs4 = kv4 + Nn*5 + 1;
    int slice = blockIdx.y;
    int hb = slice / Tt, t = slice % Tt;
    int h = hb / Bb, b = hb % Bb;
    size_t sl_off = ((size_t)(b*Tt + t)*Nn)*Dd + h*HDm;
    const float* kbase = g_k2 + sl_off;
    const float* vbase = g_v2 + sl_off;
    const float* qbase = g_q2 + sl_off;
    for (int idx = threadIdx.x; idx < Nn*4; idx += 256) {
        int n = idx >> 2, q = idx & 3;
        Ks4[n*5 + q] = *(const float4*)(kbase + (size_t)n*Dd + q*4);
        Vs4[n*5 + q] = *(const float4*)(vbase + (size_t)n*Dd + q*4);
    }
    __syncthreads();

    int warp = threadIdx.x >> 5, lane = threadIdx.x & 31;
    int rstart = blockIdx.x * 77;
    int rend = min(Nn, rstart + 77);
    const __nv_bfloat16* dynb = g_dynb + (size_t)slice*SLICE_CP;

    for (int n = rstart + warp; n < rend; n += 8) {
        float4 qn[4];
        #pragma unroll
        for (int q = 0; q < 4; q++) qn[q] = *(const float4*)(qbase + (size_t)n*Dd + q*4);
        float e[10]; float mx = -1e30f;
        #pragma unroll
        for (int k = 0; k < 10; k++) {
            int m = lane + 32*k;
            float s = -1e30f;
            if (m < Nn) {
                float a = 0.f;
                #pragma unroll
                for (int q = 0; q < 4; q++) {
                    float4 km = Ks4[m*5 + q];
                    a += qn[q].x*km.x + qn[q].y*km.y + qn[q].z*km.z + qn[q].w*km.w;
                }
                s = (a * 0.25f) * __bfloat162float(dynb[(size_t)n*LDP + m]);
            }
            e[k] = s; mx = fmaxf(mx, s);
        }
        #pragma unroll
        for (int o = 16; o; o >>= 1) mx = fmaxf(mx, __shfl_xor_sync(0xffffffffu, mx, o));
        float sum = 0.f;
        #pragma unroll
        for (int k = 0; k < 10; k++) { float v = __expf(e[k] - mx); e[k] = v; sum += v; }
        #pragma unroll
        for (int o = 16; o; o >>= 1) sum += __shfl_xor_sync(0xffffffffu, sum, o);
        float inv = 1.f / sum;

        float4 acc[4];
        #pragma unroll
        for (int q = 0; q < 4; q++) acc[q] = make_float4(0.f, 0.f, 0.f, 0.f);
        #pragma unroll
        for (int k = 0; k < 10; k++) {
            int m = lane + 32*k;
            if (m < Nn) {
                float w = e[k]*inv;
                #pragma unroll
                for (int q = 0; q < 4; q++) {
                    float4 vm = Vs4[m*5 + q];
                    acc[q].x += w*vm.x; acc[q].y += w*vm.y;
                    acc[q].z += w*vm.z; acc[q].w += w*vm.w;
                }
            }
        }
        float* accf = (float*)acc;
        #pragma unroll
        for (int d = 0; d < 16; d++) {
            #pragma unroll
            for (int o = 16; o; o >>= 1) accf[d] += __shfl_xor_sync(0xffffffffu, accf[d], o);
        }
        if (lane < 16) {
            size_t oidx = ((size_t)(b*Tt + t)*Nn + n)*Dd + h*HDm + lane;
            out[oidx] = g_out1h[oidx] + 0.5f * tanhf(accf[lane]);
        }
    }
}

// ---------------- launch: fork-join DAG across two streams -----------------
extern "C" void kernel_launch(void* const* d_in, const int* in_sizes, int n_in,
                              void* d_out, int out_size) {
    const float* query  = (const float*)d_in[0];
    const float* key_in = (const float*)d_in[1];
    const float* value  = (const float*)d_in[2];
    const float* adj    = (const float*)d_in[3];
    const float* Eg     = (const float*)d_in[4];
    const float* Wq     = (const float*)d_in[5];
    const float* bq     = (const float*)d_in[6];
    const float* Wk     = (const float*)d_in[7];
    const float* bk     = (const float*)d_in[8];
    const float* Wv     = (const float*)d_in[9];
    const float* bv     = (const float*)d_in[10];
    const float* Wt     = (const float*)d_in[11];
    const float* bt     = (const float*)d_in[12];
    float* out = (float*)d_out;

    cudaFuncSetAttribute(dyn_gemm_tc,
                         cudaFuncAttributeMaxDynamicSharedMemorySize, DYN_SMEM_BYTES);
    cudaFuncSetAttribute(graphconv_tc,
                         cudaFuncAttributeMaxDynamicSharedMemorySize, GC_SMEM_BYTES);
    cudaFuncSetAttribute(attn_kernel,
                         cudaFuncAttributeMaxDynamicSharedMemorySize, ATTN_SMEM_BYTES);

    // kernel_launch is invoked only a handful of times (correctness + capture),
    // so fresh stream/event creation per call is cheap and deterministic.
    // They are intentionally not destroyed: destroying a stream/event that
    // participated in an ongoing capture would invalidate the graph.
    cudaStream_t s1;
    cudaStreamCreateWithFlags(&s1, cudaStreamNonBlocking);
    cudaEvent_t e0, e1;
    cudaEventCreateWithFlags(&e0, cudaEventDisableTiming);
    cudaEventCreateWithFlags(&e1, cudaEventDisableTiming);

    // fork: s1 joins the capture DAG
    cudaEventRecord(e0, 0);
    cudaStreamWaitEvent(s1, e0, 0);

    // Chain B on s1: egpack -> pmat -> dyn
    egpack_kernel<<<LDP, 256, 0, s1>>>(Eg);
    pmat_kernel<<<dim3(4, NSLICE), 256, 0, s1>>>(query);
    dyn_gemm_tc<<<dim3(5, 3, NSLICE), 256, DYN_SMEM_BYTES, s1>>>();

    // Chain A on default stream: nadj -> linear -> graphconv
    nadj_kernel<<<Nn, 256>>>(adj);
    linear_kernel<<<dim3((BTN + 63)/64, 1, 4), 256>>>(query, key_in, value,
                                                      Wq, bq, Wk, bk, Wv, bv, Wt);
    graphconv_tc<<<dim3(Bb*Tt, 3), 256, GC_SMEM_BYTES>>>(bt);

    // join: attn needs both chains
    cudaEventRecord(e1, s1);
    cudaStreamWaitEvent(0, e1, 0);
    attn_kernel<<<dim3(4, NSLICE), 256, ATTN_SMEM_BYTES>>>(out);
}